// round 10
// baseline (speedup 1.0000x reference)
#include <cuda_runtime.h>
#include <cuda_fp16.h>
#include <cstdint>

#define B_ 32
#define D_ 256
#define T_ 2048
#define K_ 1024
#define N_ (B_ * T_)            // 65536 vectors
#define QSIZE (B_ * D_ * T_)    // 16777216 quantized elements

// ---------------- device scratch (no allocation allowed) -------------------
__device__ float  g_e2[K_];
__device__ float  g_x2[N_];
__device__ int    g_idx[N_];
__device__ double g_loss;
// Pre-split codebook (scaled by 2^14): e*2^14 = h + l (residual <= 2^-24 rel)
__device__ __align__(16) __half g_eh[K_ * D_];
__device__ __align__(16) __half g_el[K_ * D_];

#define SCALE_X 16.0f            // 2^4
#define SCALE_E 16384.0f         // 2^14
#define UNSCALE_M2 (-7.62939453125e-6f)   // -2 * 2^-18, exact power of two

// ---------------- smem layout (dynamic) -------------------------------------
// A: [split 0..1][kc 0..3] 16KB tiles of [128 tok][64 d fp16, swizzled rows]
#define SMA   0                  // 131072 bytes
// B chunk ring: 3 x 16KB; chunk = [split 0..1][64 code rows x 128B (64 d)]
#define SMB0  131072
#define SME2  180224             // 1024 floats (full e2 table)
#define SMRV  184320             // 128*2 floats
#define SMRI  185344             // 128*2 ints
#define SMTOT 186368

__device__ __forceinline__ uint32_t smem_u32(const void* p) {
    uint32_t a;
    asm("{ .reg .u64 t; cvta.to.shared.u64 t, %1; cvt.u32.u64 %0, t; }"
        : "=r"(a) : "l"(p));
    return a;
}
__device__ __forceinline__ void ldsm_x4(uint32_t addr, uint32_t* r) {
    asm volatile(
        "ldmatrix.sync.aligned.m8n8.x4.shared.b16 {%0,%1,%2,%3}, [%4];"
        : "=r"(r[0]), "=r"(r[1]), "=r"(r[2]), "=r"(r[3]) : "r"(addr));
}
__device__ __forceinline__ void mma16816(float* c, const uint32_t* a,
                                         const uint32_t* b) {
    asm volatile(
        "mma.sync.aligned.m16n8k16.row.col.f32.f16.f16.f32 "
        "{%0,%1,%2,%3}, {%4,%5,%6,%7}, {%8,%9}, {%0,%1,%2,%3};"
        : "+f"(c[0]), "+f"(c[1]), "+f"(c[2]), "+f"(c[3])
        : "r"(a[0]), "r"(a[1]), "r"(a[2]), "r"(a[3]), "r"(b[0]), "r"(b[1]));
}
__device__ __forceinline__ void cp16(uint32_t dst, const void* src) {
    asm volatile("cp.async.cg.shared.global [%0], [%1], 16;"
                 :: "r"(dst), "l"(src));
}

// ---------------------------------------------------------------------------
// Kernel 1: fused codebook prep: e2[k] (fl32 squares, double-accum) and
// fp16 hi/lo split of e*2^14. Also zeroes the loss accumulator.
// ---------------------------------------------------------------------------
__global__ void prepE_kernel(const float* __restrict__ E) {
    int k = blockIdx.x;
    int d = threadIdx.x;
    size_t o = (size_t)k * D_ + d;
    float v = E[o];

    float es = __fmul_rn(v, SCALE_E);           // exact power-of-2 scale
    __half h = __float2half_rn(es);
    __half l = __float2half_rn(__fsub_rn(es, __half2float(h)));
    g_eh[o] = h;
    g_el[o] = l;

    float sq = __fmul_rn(v, v);
    __shared__ double s[256];
    s[d] = (double)sq;
    __syncthreads();
    for (int off = 128; off > 0; off >>= 1) {
        if (d < off) s[d] += s[d + off];
        __syncthreads();
    }
    if (d == 0) g_e2[k] = (float)s[0];
    if (k == 0 && d == 0) g_loss = 0.0;
}

// ---------------------------------------------------------------------------
// Kernel 1b: x2[n] per vector (double accumulation of fl32 squares).
// ---------------------------------------------------------------------------
__global__ __launch_bounds__(256) void x2_kernel(const float* __restrict__ X) {
    int b = blockIdx.y;
    int t = blockIdx.x * 256 + threadIdx.x;
    const float* xp = X + (size_t)b * (D_ * T_) + t;
    double acc = 0.0;
#pragma unroll 8
    for (int d = 0; d < D_; d++) {
        float x = xp[(size_t)d * T_];
        acc += (double)__fmul_rn(x, x);
    }
    g_x2[b * T_ + t] = (float)acc;
}

// ---------------------------------------------------------------------------
// Kernel 2: HMMA distance GEMM + argmin; 3-stage cp.async chunk pipeline.
// CTA = 128 tokens, 8 warps: wm = wid&3 (32-token group), wn = wid>>2
// (32-code half of the current 64-code tile). 64 chunks = 16 code-tiles x
// 4 kc (64-d) slices; acc[2][4][4] persists across the 4 kc of a tile.
// dot = (AhBh + AhBl + AlBh) with fp16 splits of scaled x,e; fp32 accum.
// Epilogue: dist = fl(fl(x2+e2) - 2*fl(dot)); strict <, tie -> smaller k.
// ---------------------------------------------------------------------------
__global__ __launch_bounds__(256, 1)
void argmin_mma_kernel(const float* __restrict__ X) {
    extern __shared__ char smem[];
    const uint32_t sb = smem_u32(smem);
    const int tid  = threadIdx.x;
    const int lane = tid & 31, wid = tid >> 5;
    const int wm = wid & 3, wn = wid >> 2;
    const int bx = blockIdx.x;
    const int b  = bx >> 4, t0 = (bx & 15) * 128;
    const int n0 = b * T_ + t0;
    const float* Xb = X + (size_t)b * (D_ * T_) + t0;

    // ---- stage A: X tile -> fp16 h/l (scaled by 2^4), swizzled [tok][d] ---
#pragma unroll 4
    for (int i = 0; i < 16; i++) {
        int idx = tid + i * 256;          // 0..4095
        int kc  = idx >> 10;              // 0..3
        int rem = idx & 1023;
        int dp  = rem >> 5;               // d-pair 0..31
        int c4  = rem & 31;               // float4 over tok
        int dg  = kc * 64 + dp * 2;
        float4 va = *(const float4*)(Xb + (size_t)dg * T_ + c4 * 4);
        float4 vb = *(const float4*)(Xb + (size_t)(dg + 1) * T_ + c4 * 4);
        float fa[4] = {va.x, va.y, va.z, va.w};
        float fb[4] = {vb.x, vb.y, vb.z, vb.w};
#pragma unroll
        for (int u = 0; u < 4; u++) {
            int tok = c4 * 4 + u;
            float x0 = __fmul_rn(fa[u], SCALE_X);
            float x1 = __fmul_rn(fb[u], SCALE_X);
            __half h0 = __float2half_rn(x0);
            __half l0 = __float2half_rn(__fsub_rn(x0, __half2float(h0)));
            __half h1 = __float2half_rn(x1);
            __half l1 = __float2half_rn(__fsub_rn(x1, __half2float(h1)));
            uint32_t off = (uint32_t)(tok * 128 + ((dp * 4) ^ ((tok & 7) << 4)));
            *(uint32_t*)(smem + SMA + kc * 16384 + off) =
                (uint32_t)__half_as_ushort(h0) |
                ((uint32_t)__half_as_ushort(h1) << 16);
            *(uint32_t*)(smem + SMA + 65536 + kc * 16384 + off) =
                (uint32_t)__half_as_ushort(l0) |
                ((uint32_t)__half_as_ushort(l1) << 16);
        }
    }
    // stage full e2 table (read only after later barriers)
    {
        float* se2w = (float*)(smem + SME2);
#pragma unroll
        for (int i = 0; i < 4; i++) se2w[tid + i * 256] = g_e2[tid + i * 256];
    }

    // per-thread owned token rows (4 slots: mb*2 + rowhalf)
    float x2own[4];
#pragma unroll
    for (int slot = 0; slot < 4; slot++) {
        int trow = wm * 32 + (slot >> 1) * 16 + (slot & 1) * 8 + (lane >> 2);
        x2own[slot] = g_x2[n0 + trow];
    }

    float best[4];
    int   bidx[4];
#pragma unroll
    for (int s = 0; s < 4; s++) { best[s] = 3.4e38f; bidx[s] = 0; }

    // lane constants for ldmatrix addressing
    const int g = lane >> 3, r = lane & 7;
    const int tok0  = wm * 32 + (g & 1) * 8 + r;   // A row (mb adds 16)
    const int khA   = g >> 1;
    const uint32_t xrA = (uint32_t)((tok0 & 7) << 4);
    const int code0 = (g >> 1) * 8 + r;            // B row within 16-block
    const int khB   = g & 1;
    const uint32_t xrB = (uint32_t)((code0 & 7) << 4);
    const uint32_t bcol = (uint32_t)((wn * 32 + code0) * 128);

    // ---- chunk prefetch: chunk c = (code-tile ct = c>>2, kc = c&3) --------
    // 16KB: [split][64 rows x 128B], 1024 x cp16, 4 per thread.
    auto prefetch = [&](int c) {
        int cbase = (c >> 2) * 64;
        int kc    = c & 3;
        uint32_t bufo = sb + SMB0 + (uint32_t)(((uint32_t)c) % 3u) * 16384;
#pragma unroll
        for (int i = 0; i < 4; i++) {
            int idx = tid + i * 256;       // 0..1023
            int s   = idx >> 9;
            int rem = idx & 511;
            int row = rem >> 3, c16 = rem & 7;
            const __half* src = (s ? g_el : g_eh)
                + (size_t)(cbase + row) * D_ + kc * 64 + c16 * 8;
            uint32_t dst = bufo + s * 8192 + row * 128
                         + (uint32_t)((c16 * 16) ^ ((row & 7) << 4));
            cp16(dst, src);
        }
        asm volatile("cp.async.commit_group;" ::: "memory");
    };

    prefetch(0);
    prefetch(1);

    const float* se2 = (const float*)(smem + SME2);
    float acc[2][4][4];

    for (int c = 0; c < 64; c++) {
        const int kc = c & 3;
        if (kc == 0) {
#pragma unroll
            for (int mb = 0; mb < 2; mb++)
#pragma unroll
                for (int nb = 0; nb < 4; nb++)
#pragma unroll
                    for (int e = 0; e < 4; e++) acc[mb][nb][e] = 0.f;
        }
        if (c == 63)
            asm volatile("cp.async.wait_group 0;" ::: "memory");
        else
            asm volatile("cp.async.wait_group 1;" ::: "memory");
        __syncthreads();   // chunk c visible to all; all done with chunk c-1

        // ---- compute chunk: 64 codes x 64 d (4 k16 steps) ----------------
        uint32_t bufo = sb + SMB0 + (uint32_t)(((uint32_t)c) % 3u) * 16384;
        uint32_t abase = sb + SMA + kc * 16384 + tok0 * 128;
        uint32_t bbase = bufo + bcol;
#pragma unroll
        for (int ks = 0; ks < 4; ks++) {
            uint32_t da = (uint32_t)((ks * 32 + khA * 16) ^ xrA);
            uint32_t db = (uint32_t)((ks * 32 + khB * 16) ^ xrB);
            uint32_t Ah[2][4], Al[2][4], Bh[2][4], Bl[2][4];
#pragma unroll
            for (int mb = 0; mb < 2; mb++) {
                ldsm_x4(abase + mb * 2048 + da, Ah[mb]);
                ldsm_x4(abase + 65536 + mb * 2048 + da, Al[mb]);
            }
#pragma unroll
            for (int n2 = 0; n2 < 2; n2++) {
                ldsm_x4(bbase + n2 * 2048 + db, Bh[n2]);
                ldsm_x4(bbase + 8192 + n2 * 2048 + db, Bl[n2]);
            }
#pragma unroll
            for (int mb = 0; mb < 2; mb++)
#pragma unroll
                for (int nb = 0; nb < 4; nb++) {
                    const uint32_t* bh = &Bh[nb >> 1][2 * (nb & 1)];
                    const uint32_t* bl = &Bl[nb >> 1][2 * (nb & 1)];
                    mma16816(acc[mb][nb], Ah[mb], bh);
                    mma16816(acc[mb][nb], Ah[mb], bl);
                    mma16816(acc[mb][nb], Al[mb], bh);
                }
        }

        if (c + 2 < 64) prefetch(c + 2);

        // ---- epilogue at tile end: exact ref rounding + running argmin ---
        if (kc == 3) {
            int cbase = (c >> 2) * 64;
#pragma unroll
            for (int mb = 0; mb < 2; mb++)
#pragma unroll
                for (int nb = 0; nb < 4; nb++)
#pragma unroll
                    for (int e = 0; e < 4; e++) {
                        int slot = mb * 2 + (e >> 1);
                        int k    = cbase + wn * 32 + nb * 8
                                 + 2 * (lane & 3) + (e & 1);
                        float C    = __fadd_rn(x2own[slot], se2[k]);
                        float m2g  = __fmul_rn(acc[mb][nb][e], UNSCALE_M2);
                        float dist = __fadd_rn(C, m2g);
                        if (dist < best[slot]) {
                            best[slot] = dist; bidx[slot] = k;
                        }
                    }
        }
    }

    // ---- reduce: 4 lanes per row (shfl), then 2 wn warps (smem) ----------
    float* rv = (float*)(smem + SMRV);
    int*   ri = (int*)(smem + SMRI);
    __syncthreads();
#pragma unroll
    for (int slot = 0; slot < 4; slot++) {
        float v = best[slot];
        int   ix = bidx[slot];
#pragma unroll
        for (int off = 1; off < 4; off <<= 1) {
            float ov = __shfl_xor_sync(0xffffffffu, v, off);
            int   oi = __shfl_xor_sync(0xffffffffu, ix, off);
            if (ov < v || (ov == v && oi < ix)) { v = ov; ix = oi; }
        }
        if ((lane & 3) == 0) {
            int trow = wm * 32 + (slot >> 1) * 16 + (slot & 1) * 8 + (lane >> 2);
            rv[trow * 2 + wn] = v;
            ri[trow * 2 + wn] = ix;
        }
    }
    __syncthreads();
    if (tid < 128) {
        float v0 = rv[tid * 2], v1 = rv[tid * 2 + 1];
        int   i0 = ri[tid * 2], i1 = ri[tid * 2 + 1];
        int sel = (v1 < v0 || (v1 == v0 && i1 < i0)) ? i1 : i0;
        g_idx[n0 + tid] = sel;
    }
}

// ---------------------------------------------------------------------------
// Kernel 3: gather codebook rows -> quantized output, fused loss.
// ---------------------------------------------------------------------------
__global__ __launch_bounds__(256) void gather_kernel(
    const float* __restrict__ X, const float* __restrict__ E,
    float* __restrict__ out)
{
    __shared__ float sq[256][33];
    __shared__ int   sidx[256];

    const int b   = blockIdx.y;
    const int t0  = blockIdx.x * 256;
    const int tid = threadIdx.x;
    const int t   = t0 + tid;

    sidx[tid] = g_idx[b * T_ + t];
    __syncthreads();

    const int rg = tid >> 3;
    const int rl = tid & 7;

    float loss = 0.f;
    for (int d0 = 0; d0 < D_; d0 += 32) {
#pragma unroll
        for (int r0 = 0; r0 < 256; r0 += 32) {
            int row = r0 + rg;
            float4 v = *reinterpret_cast<const float4*>(
                E + (size_t)sidx[row] * D_ + d0 + rl * 4);
            sq[row][rl * 4 + 0] = v.x;
            sq[row][rl * 4 + 1] = v.y;
            sq[row][rl * 4 + 2] = v.z;
            sq[row][rl * 4 + 3] = v.w;
        }
        __syncthreads();
#pragma unroll
        for (int dd = 0; dd < 32; dd++) {
            int d = d0 + dd;
            float e = sq[tid][dd];
            float x = X[((size_t)b * D_ + d) * T_ + t];
            out[((size_t)b * D_ + d) * T_ + t] = e;
            float df = e - x;
            loss = fmaf(df, df, loss);
        }
        __syncthreads();
    }

    float* s = &sq[0][0];
    s[tid] = loss;
    __syncthreads();
    for (int off = 128; off > 0; off >>= 1) {
        if (tid < off) s[tid] += s[tid + off];
        __syncthreads();
    }
    if (tid == 0) atomicAdd(&g_loss, (double)s[0]);
}

// ---------------------------------------------------------------------------
// Kernel 4: loss scalar + indices-as-float.
// loss = q_latent + 0.25 * e_latent = 1.25 * mean((q - x)^2)
// ---------------------------------------------------------------------------
__global__ void finalize_kernel(float* __restrict__ out, int out_size) {
    int i = blockIdx.x * blockDim.x + threadIdx.x;
    if (i == 0 && out_size > QSIZE) {
        out[QSIZE] = (float)(g_loss * 1.25 / (double)QSIZE);
    }
    if (i < N_ && out_size >= QSIZE + 1 + N_) {
        out[QSIZE + 1 + i] = (float)g_idx[i];
    }
}

// ---------------------------------------------------------------------------
extern "C" void kernel_launch(void* const* d_in, const int* in_sizes, int n_in,
                              void* d_out, int out_size) {
    const float* X = (const float*)d_in[0];   // [B, D, T] f32
    const float* E = (const float*)d_in[1];   // [K, D]   f32
    float* out = (float*)d_out;

    cudaFuncSetAttribute(argmin_mma_kernel,
                         cudaFuncAttributeMaxDynamicSharedMemorySize, SMTOT);

    prepE_kernel<<<K_, 256>>>(E);
    x2_kernel<<<dim3(T_ / 256, B_), 256>>>(X);
    argmin_mma_kernel<<<N_ / 128, 256, SMTOT>>>(X);
    gather_kernel<<<dim3(T_ / 256, B_), 256>>>(X, E, out);
    finalize_kernel<<<(N_ + 255) / 256, 256>>>(out, out_size);
}

// round 11
// speedup vs baseline: 1.0428x; 1.0428x over previous
#include <cuda_runtime.h>
#include <cuda_fp16.h>
#include <cstdint>

#define B_ 32
#define D_ 256
#define T_ 2048
#define K_ 1024
#define N_ (B_ * T_)            // 65536 vectors
#define QSIZE (B_ * D_ * T_)    // 16777216 quantized elements

// ---------------- device scratch (no allocation allowed) -------------------
__device__ float  g_e2[K_];
__device__ float  g_x2[N_];
__device__ int    g_idx[N_];
__device__ double g_loss;
// Pre-split codebook (scaled by 2^14): e*2^14 = h + l (residual <= 2^-24 rel)
__device__ __align__(16) __half g_eh[K_ * D_];
__device__ __align__(16) __half g_el[K_ * D_];

#define SCALE_X 16.0f            // 2^4
#define SCALE_E 16384.0f         // 2^14
#define UNSCALE_M2 (-7.62939453125e-6f)   // -2 * 2^-18, exact power of two

// ---------------- smem layout (dynamic) -------------------------------------
// A: [split 0..1][kc 0..3] 16KB tiles of [128 tok][64 d fp16, swizzled rows]
#define SMA   0                  // 131072 bytes
// B double buffer: 2 x 32KB; buf = [split 0..1][128 code rows x 128B (64 d)]
#define SMB0  131072
#define SME2  196608             // 1024 floats (full e2 table)
#define SMRV  200704             // 128*2 floats
#define SMRI  201728             // 128*2 ints
#define SMTOT 202752

__device__ __forceinline__ uint32_t smem_u32(const void* p) {
    uint32_t a;
    asm("{ .reg .u64 t; cvta.to.shared.u64 t, %1; cvt.u32.u64 %0, t; }"
        : "=r"(a) : "l"(p));
    return a;
}
__device__ __forceinline__ void ldsm_x4(uint32_t addr, uint32_t* r) {
    asm volatile(
        "ldmatrix.sync.aligned.m8n8.x4.shared.b16 {%0,%1,%2,%3}, [%4];"
        : "=r"(r[0]), "=r"(r[1]), "=r"(r[2]), "=r"(r[3]) : "r"(addr));
}
__device__ __forceinline__ void mma16816(float* c, const uint32_t* a,
                                         const uint32_t* b) {
    asm volatile(
        "mma.sync.aligned.m16n8k16.row.col.f32.f16.f16.f32 "
        "{%0,%1,%2,%3}, {%4,%5,%6,%7}, {%8,%9}, {%0,%1,%2,%3};"
        : "+f"(c[0]), "+f"(c[1]), "+f"(c[2]), "+f"(c[3])
        : "r"(a[0]), "r"(a[1]), "r"(a[2]), "r"(a[3]), "r"(b[0]), "r"(b[1]));
}
__device__ __forceinline__ void cp16(uint32_t dst, const void* src) {
    asm volatile("cp.async.cg.shared.global [%0], [%1], 16;"
                 :: "r"(dst), "l"(src));
}

// ---------------------------------------------------------------------------
// Kernel 1: fused codebook prep: e2[k] (fl32 squares, double-accum) and
// fp16 hi/lo split of e*2^14. Also zeroes the loss accumulator.
// ---------------------------------------------------------------------------
__global__ void prepE_kernel(const float* __restrict__ E) {
    int k = blockIdx.x;
    int d = threadIdx.x;
    size_t o = (size_t)k * D_ + d;
    float v = E[o];

    float es = __fmul_rn(v, SCALE_E);           // exact power-of-2 scale
    __half h = __float2half_rn(es);
    __half l = __float2half_rn(__fsub_rn(es, __half2float(h)));
    g_eh[o] = h;
    g_el[o] = l;

    float sq = __fmul_rn(v, v);
    __shared__ double s[256];
    s[d] = (double)sq;
    __syncthreads();
    for (int off = 128; off > 0; off >>= 1) {
        if (d < off) s[d] += s[d + off];
        __syncthreads();
    }
    if (d == 0) g_e2[k] = (float)s[0];
    if (k == 0 && d == 0) g_loss = 0.0;
}

// ---------------------------------------------------------------------------
// Kernel 1b: x2[n] per vector (double accumulation of fl32 squares).
// ---------------------------------------------------------------------------
__global__ __launch_bounds__(256) void x2_kernel(const float* __restrict__ X) {
    int b = blockIdx.y;
    int t = blockIdx.x * 256 + threadIdx.x;
    const float* xp = X + (size_t)b * (D_ * T_) + t;
    double acc = 0.0;
#pragma unroll 8
    for (int d = 0; d < D_; d++) {
        float x = xp[(size_t)d * T_];
        acc += (double)__fmul_rn(x, x);
    }
    g_x2[b * T_ + t] = (float)acc;
}

// ---------------------------------------------------------------------------
// Kernel 2: HMMA distance GEMM + argmin; R9-style 2-stage cp.async pipeline
// over 32KB chunks (128 codes x 64 d x 2 splits). 32 chunks = 8 code-tiles
// x 4 kc; acc[2][8][4] persists across the 4 kc of a tile.
// CTA = 128 tokens, 8 warps: wm = wid&3 (32-token group), wn = wid>>2
// (64-code half of the 128-code tile). Warp tile 32 tok x 64 codes:
// 12 LDSM : 48 HMMA per k16 step.
// dot = (AhBh + AhBl + AlBh) with fp16 splits of scaled x,e; fp32 accum.
// Epilogue: dist = fl(fl(x2+e2) - 2*fl(dot)); strict <, tie -> smaller k.
// ---------------------------------------------------------------------------
__global__ __launch_bounds__(256, 1)
void argmin_mma_kernel(const float* __restrict__ X) {
    extern __shared__ char smem[];
    const uint32_t sb = smem_u32(smem);
    const int tid  = threadIdx.x;
    const int lane = tid & 31, wid = tid >> 5;
    const int wm = wid & 3, wn = wid >> 2;
    const int bx = blockIdx.x;
    const int b  = bx >> 4, t0 = (bx & 15) * 128;
    const int n0 = b * T_ + t0;
    const float* Xb = X + (size_t)b * (D_ * T_) + t0;

    // ---- stage A: X tile -> fp16 h/l (scaled by 2^4), swizzled [tok][d] ---
#pragma unroll 4
    for (int i = 0; i < 16; i++) {
        int idx = tid + i * 256;          // 0..4095
        int kc  = idx >> 10;              // 0..3
        int rem = idx & 1023;
        int dp  = rem >> 5;               // d-pair 0..31
        int c4  = rem & 31;               // float4 over tok
        int dg  = kc * 64 + dp * 2;
        float4 va = *(const float4*)(Xb + (size_t)dg * T_ + c4 * 4);
        float4 vb = *(const float4*)(Xb + (size_t)(dg + 1) * T_ + c4 * 4);
        float fa[4] = {va.x, va.y, va.z, va.w};
        float fb[4] = {vb.x, vb.y, vb.z, vb.w};
#pragma unroll
        for (int u = 0; u < 4; u++) {
            int tok = c4 * 4 + u;
            float x0 = __fmul_rn(fa[u], SCALE_X);
            float x1 = __fmul_rn(fb[u], SCALE_X);
            __half h0 = __float2half_rn(x0);
            __half l0 = __float2half_rn(__fsub_rn(x0, __half2float(h0)));
            __half h1 = __float2half_rn(x1);
            __half l1 = __float2half_rn(__fsub_rn(x1, __half2float(h1)));
            uint32_t off = (uint32_t)(tok * 128 + ((dp * 4) ^ ((tok & 7) << 4)));
            *(uint32_t*)(smem + SMA + kc * 16384 + off) =
                (uint32_t)__half_as_ushort(h0) |
                ((uint32_t)__half_as_ushort(h1) << 16);
            *(uint32_t*)(smem + SMA + 65536 + kc * 16384 + off) =
                (uint32_t)__half_as_ushort(l0) |
                ((uint32_t)__half_as_ushort(l1) << 16);
        }
    }
    // stage full e2 table (read only after later barriers)
    {
        float* se2w = (float*)(smem + SME2);
#pragma unroll
        for (int i = 0; i < 4; i++) se2w[tid + i * 256] = g_e2[tid + i * 256];
    }

    // per-thread owned token rows (4 slots: mb*2 + rowhalf)
    float x2own[4];
#pragma unroll
    for (int slot = 0; slot < 4; slot++) {
        int trow = wm * 32 + (slot >> 1) * 16 + (slot & 1) * 8 + (lane >> 2);
        x2own[slot] = g_x2[n0 + trow];
    }

    float best[4];
    int   bidx[4];
#pragma unroll
    for (int s = 0; s < 4; s++) { best[s] = 3.4e38f; bidx[s] = 0; }

    // lane constants for ldmatrix addressing
    const int g = lane >> 3, r = lane & 7;
    const int tok0  = wm * 32 + (g & 1) * 8 + r;   // A row (mb adds 16)
    const int khA   = g >> 1;
    const uint32_t xrA = (uint32_t)((tok0 & 7) << 4);
    const int code0 = (g >> 1) * 8 + r;            // B row within 16-block
    const int khB   = g & 1;
    const uint32_t xrB = (uint32_t)((code0 & 7) << 4);
    const uint32_t bcol = (uint32_t)((wn * 64 + code0) * 128);

    // ---- chunk prefetch: chunk c = (code-tile ct = c>>2, kc = c&3) --------
    // 32KB: [split][128 rows x 128B], 2048 x cp16, 8 per thread.
    auto prefetch = [&](int c) {
        int cbase = (c >> 2) * 128;
        int kc    = c & 3;
        uint32_t bufo = sb + SMB0 + (uint32_t)(c & 1) * 32768;
#pragma unroll
        for (int i = 0; i < 8; i++) {
            int idx = tid + i * 256;       // 0..2047
            int s   = idx >> 10;
            int rem = idx & 1023;
            int row = rem >> 3, c16 = rem & 7;
            const __half* src = (s ? g_el : g_eh)
                + (size_t)(cbase + row) * D_ + kc * 64 + c16 * 8;
            uint32_t dst = bufo + s * 16384 + row * 128
                         + (uint32_t)((c16 * 16) ^ ((row & 7) << 4));
            cp16(dst, src);
        }
        asm volatile("cp.async.commit_group;" ::: "memory");
    };

    prefetch(0);

    const float* se2 = (const float*)(smem + SME2);
    float acc[2][8][4];

    for (int c = 0; c < 32; c++) {
        const int kc = c & 3;
        if (kc == 0) {
#pragma unroll
            for (int mb = 0; mb < 2; mb++)
#pragma unroll
                for (int nb = 0; nb < 8; nb++)
#pragma unroll
                    for (int e = 0; e < 4; e++) acc[mb][nb][e] = 0.f;
        }
        __syncthreads();               // all warps done reading buf (c+1)&1
        if (c + 1 < 32) {
            prefetch(c + 1);
            asm volatile("cp.async.wait_group 1;" ::: "memory");
        } else {
            asm volatile("cp.async.wait_group 0;" ::: "memory");
        }
        __syncthreads();               // chunk c visible block-wide

        // ---- compute chunk: 128 codes x 64 d (4 k16 steps) ---------------
        uint32_t bufo  = sb + SMB0 + (uint32_t)(c & 1) * 32768;
        uint32_t abase = sb + SMA + kc * 16384 + tok0 * 128;
        uint32_t bbase = bufo + bcol;
#pragma unroll
        for (int ks = 0; ks < 4; ks++) {
            uint32_t da = (uint32_t)((ks * 32 + khA * 16) ^ xrA);
            uint32_t db = (uint32_t)((ks * 32 + khB * 16) ^ xrB);
            uint32_t Ah[2][4], Al[2][4];
#pragma unroll
            for (int mb = 0; mb < 2; mb++) {
                ldsm_x4(abase + mb * 2048 + da, Ah[mb]);
                ldsm_x4(abase + 65536 + mb * 2048 + da, Al[mb]);
            }
#pragma unroll
            for (int n2 = 0; n2 < 4; n2++) {      // 16-code blocks
                uint32_t Bh[4], Bl[4];
                ldsm_x4(bbase + n2 * 2048 + db, Bh);
                ldsm_x4(bbase + 16384 + n2 * 2048 + db, Bl);
#pragma unroll
                for (int mb = 0; mb < 2; mb++)
#pragma unroll
                    for (int sub = 0; sub < 2; sub++) {
                        int nb = n2 * 2 + sub;
                        const uint32_t* bh = &Bh[2 * sub];
                        const uint32_t* bl = &Bl[2 * sub];
                        mma16816(acc[mb][nb], Ah[mb], bh);
                        mma16816(acc[mb][nb], Ah[mb], bl);
                        mma16816(acc[mb][nb], Al[mb], bh);
                    }
            }
        }

        // ---- epilogue at tile end: exact ref rounding + running argmin ---
        if (kc == 3) {
            int cbase = (c >> 2) * 128;
#pragma unroll
            for (int mb = 0; mb < 2; mb++)
#pragma unroll
                for (int nb = 0; nb < 8; nb++)
#pragma unroll
                    for (int e = 0; e < 4; e++) {
                        int slot = mb * 2 + (e >> 1);
                        int k    = cbase + wn * 64 + nb * 8
                                 + 2 * (lane & 3) + (e & 1);
                        float C    = __fadd_rn(x2own[slot], se2[k]);
                        float m2g  = __fmul_rn(acc[mb][nb][e], UNSCALE_M2);
                        float dist = __fadd_rn(C, m2g);
                        if (dist < best[slot]) {
                            best[slot] = dist; bidx[slot] = k;
                        }
                    }
        }
    }

    // ---- reduce: 4 lanes per row (shfl), then 2 wn warps (smem) ----------
    float* rv = (float*)(smem + SMRV);
    int*   ri = (int*)(smem + SMRI);
    __syncthreads();
#pragma unroll
    for (int slot = 0; slot < 4; slot++) {
        float v = best[slot];
        int   ix = bidx[slot];
#pragma unroll
        for (int off = 1; off < 4; off <<= 1) {
            float ov = __shfl_xor_sync(0xffffffffu, v, off);
            int   oi = __shfl_xor_sync(0xffffffffu, ix, off);
            if (ov < v || (ov == v && oi < ix)) { v = ov; ix = oi; }
        }
        if ((lane & 3) == 0) {
            int trow = wm * 32 + (slot >> 1) * 16 + (slot & 1) * 8 + (lane >> 2);
            rv[trow * 2 + wn] = v;
            ri[trow * 2 + wn] = ix;
        }
    }
    __syncthreads();
    if (tid < 128) {
        float v0 = rv[tid * 2], v1 = rv[tid * 2 + 1];
        int   i0 = ri[tid * 2], i1 = ri[tid * 2 + 1];
        int sel = (v1 < v0 || (v1 == v0 && i1 < i0)) ? i1 : i0;
        g_idx[n0 + tid] = sel;
    }
}

// ---------------------------------------------------------------------------
// Kernel 3: gather codebook rows -> quantized output, fused loss.
// ---------------------------------------------------------------------------
__global__ __launch_bounds__(256) void gather_kernel(
    const float* __restrict__ X, const float* __restrict__ E,
    float* __restrict__ out)
{
    __shared__ float sq[256][33];
    __shared__ int   sidx[256];

    const int b   = blockIdx.y;
    const int t0  = blockIdx.x * 256;
    const int tid = threadIdx.x;
    const int t   = t0 + tid;

    sidx[tid] = g_idx[b * T_ + t];
    __syncthreads();

    const int rg = tid >> 3;
    const int rl = tid & 7;

    float loss = 0.f;
    for (int d0 = 0; d0 < D_; d0 += 32) {
#pragma unroll
        for (int r0 = 0; r0 < 256; r0 += 32) {
            int row = r0 + rg;
            float4 v = *reinterpret_cast<const float4*>(
                E + (size_t)sidx[row] * D_ + d0 + rl * 4);
            sq[row][rl * 4 + 0] = v.x;
            sq[row][rl * 4 + 1] = v.y;
            sq[row][rl * 4 + 2] = v.z;
            sq[row][rl * 4 + 3] = v.w;
        }
        __syncthreads();
#pragma unroll
        for (int dd = 0; dd < 32; dd++) {
            int d = d0 + dd;
            float e = sq[tid][dd];
            float x = X[((size_t)b * D_ + d) * T_ + t];
            out[((size_t)b * D_ + d) * T_ + t] = e;
            float df = e - x;
            loss = fmaf(df, df, loss);
        }
        __syncthreads();
    }

    float* s = &sq[0][0];
    s[tid] = loss;
    __syncthreads();
    for (int off = 128; off > 0; off >>= 1) {
        if (tid < off) s[tid] += s[tid + off];
        __syncthreads();
    }
    if (tid == 0) atomicAdd(&g_loss, (double)s[0]);
}

// ---------------------------------------------------------------------------
// Kernel 4: loss scalar + indices-as-float.
// loss = q_latent + 0.25 * e_latent = 1.25 * mean((q - x)^2)
// ---------------------------------------------------------------------------
__global__ void finalize_kernel(float* __restrict__ out, int out_size) {
    int i = blockIdx.x * blockDim.x + threadIdx.x;
    if (i == 0 && out_size > QSIZE) {
        out[QSIZE] = (float)(g_loss * 1.25 / (double)QSIZE);
    }
    if (i < N_ && out_size >= QSIZE + 1 + N_) {
        out[QSIZE + 1 + i] = (float)g_idx[i];
    }
}

// ---------------------------------------------------------------------------
extern "C" void kernel_launch(void* const* d_in, const int* in_sizes, int n_in,
                              void* d_out, int out_size) {
    const float* X = (const float*)d_in[0];   // [B, D, T] f32
    const float* E = (const float*)d_in[1];   // [K, D]   f32
    float* out = (float*)d_out;

    cudaFuncSetAttribute(argmin_mma_kernel,
                         cudaFuncAttributeMaxDynamicSharedMemorySize, SMTOT);

    prepE_kernel<<<K_, 256>>>(E);
    x2_kernel<<<dim3(T_ / 256, B_), 256>>>(X);
    argmin_mma_kernel<<<N_ / 128, 256, SMTOT>>>(X);
    gather_kernel<<<dim3(T_ / 256, B_), 256>>>(X, E, out);
    finalize_kernel<<<(N_ + 255) / 256, 256>>>(out, out_size);
}